// round 16
// baseline (speedup 1.0000x reference)
#include <cuda_runtime.h>
#include <cuda_bf16.h>
#include <math.h>
#include <stdint.h>

#define BB   16
#define CC   512
#define HWW  1024
#define NCAPS 8
#define CAPC 32
#define OC   256
#define TAPS 81
#define SLOTS 64
#define TOPK  8
#define KSPLIT 8

// ================= helpers =================
__device__ __forceinline__ uint32_t smem_u32(const void* p) {
    uint32_t a;
    asm("{ .reg .u64 t; cvta.to.shared.u64 t, %1; cvt.u32.u64 %0, t; }" : "=r"(a) : "l"(p));
    return a;
}
#define CP_ASYNC16(dst, src) \
    asm volatile("cp.async.cg.shared.global [%0], [%1], 16;" :: "r"(dst), "l"(src) : "memory")
#define CP_COMMIT() asm volatile("cp.async.commit_group;" ::: "memory")
#define CP_WAIT0()  asm volatile("cp.async.wait_group 0;" ::: "memory")
#define CP_WAIT1()  asm volatile("cp.async.wait_group 1;" ::: "memory")

__device__ __forceinline__ void ldsm_x4(uint32_t* r, uint32_t addr) {
    asm volatile("ldmatrix.sync.aligned.m8n8.x4.shared.b16 {%0,%1,%2,%3}, [%4];"
                 : "=r"(r[0]), "=r"(r[1]), "=r"(r[2]), "=r"(r[3]) : "r"(addr));
}
__device__ __forceinline__ void mma_bf16(float* c, const uint32_t* a, const uint32_t* b) {
    asm volatile("mma.sync.aligned.m16n8k16.row.col.f32.bf16.bf16.f32 "
                 "{%0,%1,%2,%3}, {%4,%5,%6,%7}, {%8,%9}, {%0,%1,%2,%3};"
                 : "+f"(c[0]), "+f"(c[1]), "+f"(c[2]), "+f"(c[3])
                 : "r"(a[0]), "r"(a[1]), "r"(a[2]), "r"(a[3]), "r"(b[0]), "r"(b[1]));
}
__device__ __forceinline__ void mma_s8(int* c, const uint32_t* a, const uint32_t* b) {
    asm volatile("mma.sync.aligned.m16n8k32.row.col.s32.s8.s8.s32 "
                 "{%0,%1,%2,%3}, {%4,%5,%6,%7}, {%8,%9}, {%0,%1,%2,%3};"
                 : "+r"(c[0]), "+r"(c[1]), "+r"(c[2]), "+r"(c[3])
                 : "r"(a[0]), "r"(a[1]), "r"(a[2]), "r"(a[3]), "r"(b[0]), "r"(b[1]));
}
__device__ __forceinline__ uint32_t swz64(uint32_t o) { return o ^ ((o >> 3) & 0x70); }

// ================= scratch =================
__device__ __align__(128) float g_x[BB * CC * HWW];
__device__ float g_cap4[2 * BB * NCAPS * HWW];   // two c-half slices
__device__ int   g_idx[BB * NCAPS];
__device__ int   g_slots[BB * SLOTS];
__device__ float g_rpart[KSPLIT * BB * OC * SLOTS];
__device__ float g_norm[BB * HWW];
__device__ float g_smean[CC * NCAPS];
__device__ float g_cm[BB * NCAPS * HWW];
__device__ float g_mm[BB * NCAPS * 2];
__device__ float g_cmmean[BB * HWW];
__device__ float g_proto[NCAPS * CC];
__device__ float g_pm[CC];
__device__ __align__(128) __nv_bfloat16 g_w_hi[TAPS * OC * CC];
__device__ __align__(128) __nv_bfloat16 g_w_lo[TAPS * OC * CC];
// int8 operands (halo of padded x planes never written -> zero from BSS)
__device__ __align__(128) int8_t g_w_s8[TAPS * OC * CC];
__device__ __align__(128) int8_t g_w16h[TAPS * OC * CC];
__device__ __align__(128) int8_t g_w16l[TAPS * OC * CC];
__device__ __align__(128) int8_t g_xp_s8[BB * 40 * 40 * CC];
__device__ __align__(128) int8_t g_x16h[BB * 40 * 40 * CC];
__device__ __align__(128) int8_t g_x16l[BB * 40 * 40 * CC];
__device__ unsigned int g_wmax_bits;
__device__ unsigned int g_xmax_bits;
__device__ __align__(128) __nv_bfloat16 g_cw_hi[CC * CC];
__device__ __align__(128) __nv_bfloat16 g_cw_lo[CC * CC];
__device__ __align__(128) __nv_bfloat16 g_x5t_hi[BB * HWW * CC];
__device__ __align__(128) __nv_bfloat16 g_x5t_lo[BB * HWW * CC];

// ================= KP_PRE: kp5 (blocks 0..511) + kp_w1 (512..1535) ==========
__global__ __launch_bounds__(256) void kp_pre(const float* __restrict__ x5,
                                              const float* __restrict__ w) {
    __shared__ float tile[32][33];
    int tid = threadIdx.x;
    if (blockIdx.x >= 512) {
        int i = (blockIdx.x - 512) * 256 + tid;
        float v = w[i];
        __nv_bfloat16 h = __float2bfloat16(v);
        g_cw_hi[i] = h;
        g_cw_lo[i] = __float2bfloat16(v - __bfloat162float(h));
        return;
    }
    int b = blockIdx.x >> 5, h = blockIdx.x & 31;
    for (int c0 = 0; c0 < CC; c0 += 32) {
#pragma unroll
        for (int s = 0; s < 4; s++) {
            int cl = (tid >> 5) + s * 8, w_ = tid & 31;
            tile[cl][w_] = x5[((size_t)(b * CC + c0 + cl)) * HWW + h * 32 + w_];
        }
        __syncthreads();
#pragma unroll
        for (int s = 0; s < 4; s++) {
            int wl = (tid >> 5) + s * 8, ci = tid & 31;
            float v = tile[ci][wl];
            size_t dst = ((size_t)(b * HWW + h * 32 + wl)) * CC + c0 + ci;
            __nv_bfloat16 hh = __float2bfloat16(v);
            g_x5t_hi[dst] = hh;
            g_x5t_lo[dst] = __float2bfloat16(v - __bfloat162float(hh));
        }
        __syncthreads();
    }
}

// ================= K1: split-bf16 mma ======================================
#define K1_STG 49152u
#define K1_SMEM 98304
__global__ __launch_bounds__(256, 1) void k1_mma(const float* __restrict__ x5,
                                                 const float* __restrict__ bias) {
    extern __shared__ char smem[];
    uint32_t sb = smem_u32(smem);
    int tid = threadIdx.x, wid = tid >> 5, lane = tid & 31;
    int pix0 = blockIdx.x * 256;
    int ocb  = blockIdx.y * 128;
    int b    = blockIdx.z;
    int mbase = (wid >> 2) * 64;
    int nbase = (wid & 3) * 64;

    float acc[4][8][4];
#pragma unroll
    for (int mt = 0; mt < 4; mt++)
#pragma unroll
        for (int nt = 0; nt < 8; nt++)
#pragma unroll
            for (int j = 0; j < 4; j++) acc[mt][nt][j] = 0.f;

    auto issue = [&](int kch, int s) {
        uint32_t stg = sb + (uint32_t)s * K1_STG;
#pragma unroll
        for (int p = 0; p < 4; p++) {
            int e = tid + p * 256;
            int plane = e >> 9, r = (e >> 2) & 127, kc = e & 3;
            size_t gsrc = (size_t)(ocb + r) * CC + kch * 32 + kc * 8;
            const __nv_bfloat16* src = (plane ? g_cw_lo : g_cw_hi) + gsrc;
            CP_ASYNC16(stg + (uint32_t)plane * 8192u + swz64((uint32_t)(r * 64 + kc * 16)),
                       (const void*)src);
        }
#pragma unroll
        for (int p = 0; p < 8; p++) {
            int e = tid + p * 256;
            int plane = e >> 10, row = (e >> 2) & 255, kc = e & 3;
            size_t gsrc = ((size_t)(b * HWW + pix0 + row)) * CC + kch * 32 + kc * 8;
            const __nv_bfloat16* src = (plane ? g_x5t_lo : g_x5t_hi) + gsrc;
            CP_ASYNC16(stg + 16384u + (uint32_t)plane * 16384u + swz64((uint32_t)(row * 64 + kc * 16)),
                       (const void*)src);
        }
    };

    issue(0, 0);
    CP_COMMIT();
    for (int kch = 0; kch < 16; kch++) {
        int s = kch & 1;
        if (kch + 1 < 16) issue(kch + 1, s ^ 1);
        CP_COMMIT();
        CP_WAIT1();
        __syncthreads();
        uint32_t stg = sb + (uint32_t)s * K1_STG;
#pragma unroll
        for (int kb = 0; kb < 2; kb++) {
            uint32_t ah[4][4], al[4][4];
#pragma unroll
            for (int mt = 0; mt < 4; mt++) {
                int arow = mbase + mt * 16 + (lane & 15);
                int kcs = kb * 2 + (lane >> 4);
                uint32_t so = swz64((uint32_t)(arow * 64 + kcs * 16));
                ldsm_x4(ah[mt], stg + so);
                ldsm_x4(al[mt], stg + 8192u + so);
            }
#pragma unroll
            for (int ntp = 0; ntp < 4; ntp++) {
                int m = lane >> 3;
                int row = nbase + ntp * 16 + ((m & 2) << 2) + (lane & 7);
                int kcs = kb * 2 + (m & 1);
                uint32_t so = swz64((uint32_t)(row * 64 + kcs * 16));
                uint32_t bh[4], bl[4];
                ldsm_x4(bh, stg + 16384u + so);
                ldsm_x4(bl, stg + 32768u + so);
#pragma unroll
                for (int mt = 0; mt < 4; mt++) {
                    mma_bf16(acc[mt][2 * ntp],     ah[mt], bh);
                    mma_bf16(acc[mt][2 * ntp],     ah[mt], bl);
                    mma_bf16(acc[mt][2 * ntp],     al[mt], bh);
                    mma_bf16(acc[mt][2 * ntp + 1], ah[mt], bh + 2);
                    mma_bf16(acc[mt][2 * ntp + 1], ah[mt], bl + 2);
                    mma_bf16(acc[mt][2 * ntp + 1], al[mt], bh + 2);
                }
            }
        }
        __syncthreads();
    }
    float am = 0.f;
#pragma unroll
    for (int mt = 0; mt < 4; mt++) {
        int m0 = ocb + mbase + mt * 16 + (lane >> 2);
        float bi0 = bias[m0], bi1 = bias[m0 + 8];
        size_t base0 = ((size_t)(b * CC + m0)) * HWW + pix0;
        size_t base1 = ((size_t)(b * CC + m0 + 8)) * HWW + pix0;
#pragma unroll
        for (int nt = 0; nt < 8; nt++) {
            int n = nbase + nt * 8 + (lane & 3) * 2;
            float v0 = acc[mt][nt][0] + bi0 + x5[base0 + n];
            float v1 = acc[mt][nt][1] + bi0 + x5[base0 + n + 1];
            float v2 = acc[mt][nt][2] + bi1 + x5[base1 + n];
            float v3 = acc[mt][nt][3] + bi1 + x5[base1 + n + 1];
            g_x[base0 + n]     = v0;
            g_x[base0 + n + 1] = v1;
            g_x[base1 + n]     = v2;
            g_x[base1 + n + 1] = v3;
            am = fmaxf(am, fmaxf(fmaxf(fabsf(v0), fabsf(v1)), fmaxf(fabsf(v2), fabsf(v3))));
        }
    }
#pragma unroll
    for (int off = 16; off; off >>= 1)
        am = fmaxf(am, __shfl_xor_sync(0xffffffffu, am, off));
    if (lane == 0) atomicMax(&g_xmax_bits, __float_as_uint(am));
}

// ================= KPW ======================================================
__global__ __launch_bounds__(256) void kp_w(const float* __restrict__ cw) {
    __shared__ float tile[64 * 81];
    __shared__ float red[256];
    int o  = blockIdx.x >> 3;
    int c0 = (blockIdx.x & 7) * 64;
    int tid = threadIdx.x;
    for (int e = tid; e < 64 * 81; e += 256) {
        int c_l = e / 81, t = e - c_l * 81;
        tile[e] = cw[((size_t)o * CC + c0 + c_l) * TAPS + t];
    }
    __syncthreads();
    float amax = 0.f;
    for (int e = tid; e < 81 * 64; e += 256) {
        int t = e >> 6, c_l = e & 63;
        float v = tile[c_l * 81 + t];
        amax = fmaxf(amax, fabsf(v));
        __nv_bfloat16 h = __float2bfloat16(v);
        size_t di = ((size_t)(t * OC + o)) * CC + c0 + c_l;
        g_w_hi[di] = h;
        g_w_lo[di] = __float2bfloat16(v - __bfloat162float(h));
    }
    red[tid] = amax;
    __syncthreads();
    for (int s = 128; s > 0; s >>= 1) {
        if (tid < s) red[tid] = fmaxf(red[tid], red[tid + s]);
        __syncthreads();
    }
    if (tid == 0) atomicMax(&g_wmax_bits, __float_as_uint(red[0]));
}

// ================= KP_WQ: quantize weights (int8 rank + int16 pair) =========
__global__ void kp_wq() {
    float wmax = __uint_as_float(g_wmax_bits);
    float qi8  = 127.f / wmax;
    float qi16 = 32639.f / wmax;
    int i = blockIdx.x * 256 + threadIdx.x;
    uint4 h = ((const uint4*)g_w_hi)[i];
    uint4 l = ((const uint4*)g_w_lo)[i];
    const __nv_bfloat16* hp = (const __nv_bfloat16*)&h;
    const __nv_bfloat16* lp = (const __nv_bfloat16*)&l;
    char r8[8], rh[8], rl[8];
#pragma unroll
    for (int j = 0; j < 8; j++) {
        float v = __bfloat162float(hp[j]) + __bfloat162float(lp[j]);
        int q = __float2int_rn(v * qi8);
        r8[j] = (char)max(-127, min(127, q));
        int q16 = __float2int_rn(v * qi16);
        q16 = max(-32639, min(32639, q16));
        int qh = (q16 + 128) >> 8;
        rh[j] = (char)qh;
        rl[j] = (char)(q16 - (qh << 8));
    }
    ((uint2*)g_w_s8)[i] = *(uint2*)r8;
    ((uint2*)g_w16h)[i] = *(uint2*)rh;
    ((uint2*)g_w16l)[i] = *(uint2*)rl;
}

// ================= KPX: transpose g_x -> int8 planes + norm =================
__global__ __launch_bounds__(256) void kp_x() {
    __shared__ float tile[32][33];
    int b = blockIdx.y, h = blockIdx.x;
    int tid = threadIdx.x;
    int lane = tid & 31;
    float xmax = __uint_as_float(g_xmax_bits);
    float qi8  = 127.f / xmax;
    float qi16 = 32639.f / xmax;
    float nsum[4] = {0.f, 0.f, 0.f, 0.f};
    for (int c0 = 0; c0 < CC; c0 += 32) {
#pragma unroll
        for (int s = 0; s < 4; s++) {
            int cl = (tid >> 5) + s * 8, w = tid & 31;
            tile[cl][w] = g_x[((size_t)(b * CC + c0 + cl)) * HWW + h * 32 + w];
        }
        __syncthreads();
#pragma unroll
        for (int s = 0; s < 4; s++) {
            int wl = (tid >> 5) + s * 8, ci = lane;
            float v = tile[ci][wl];
            size_t dst = ((size_t)((b * 40 + h + 4) * 40 + wl + 4)) * CC + c0 + ci;
            int q = __float2int_rn(v * qi8);
            g_xp_s8[dst] = (int8_t)max(-127, min(127, q));
            int q16 = __float2int_rn(v * qi16);
            q16 = max(-32639, min(32639, q16));
            int qh = (q16 + 128) >> 8;
            g_x16h[dst] = (int8_t)qh;
            g_x16l[dst] = (int8_t)(q16 - (qh << 8));
            float vv = v * v;
#pragma unroll
            for (int off = 16; off; off >>= 1)
                vv += __shfl_xor_sync(0xffffffffu, vv, off);
            nsum[s] += vv;
        }
        __syncthreads();
    }
    if (lane == 0) {
#pragma unroll
        for (int s = 0; s < 4; s++)
            g_norm[b * HWW + h * 32 + (tid >> 5) + s * 8] = sqrtf(nsum[s]);
    }
}

// ================= K2a: int8 ranking conv + fused squash/max ================
// A rows permuted: tile y row r -> oc = (r&7)*32 + (r>>3) + 16*y
#define S8_BSTR  10240u
#define S8_BBUF  20480u
#define S8_ABASE 40960u
#define S8_ROW   36864u
#define K2A_SMEM 188416
__global__ __launch_bounds__(256, 1) void k2a_s8(const float* __restrict__ cb) {
    extern __shared__ char smem[];
    uint32_t sb = smem_u32(smem);
    int tid = threadIdx.x, wid = tid >> 5, lane = tid & 31;
    int bh8  = blockIdx.x * 8;
    int pix0 = blockIdx.x * 256;
    int y    = blockIdx.y;
    int b    = blockIdx.z;
    int mbase = (wid >> 2) * 64;
    int nbase = (wid & 3) * 64;

    int acc[4][8][4];
#pragma unroll
    for (int mt = 0; mt < 4; mt++)
#pragma unroll
        for (int nt = 0; nt < 8; nt++)
#pragma unroll
            for (int j = 0; j < 4; j++) acc[mt][nt][j] = 0;

    int r_ = tid >> 1, kc_ = tid & 1;
    int ocPerm = ((r_ & 7) << 5) + (r_ >> 3) + 16 * y;
    auto issueRow = [&](int R) {
        int q = R / 9, dy = R - q * 9;
        uint32_t buf = sb + S8_ABASE + (uint32_t)(R & 3) * S8_ROW;
#pragma unroll
        for (int p = 0; p < 9; p++) {
            const int8_t* src = g_w_s8 +
                ((size_t)((dy * 9 + p) * OC + ocPerm)) * CC + q * 32 + kc_ * 16;
            CP_ASYNC16(buf + (uint32_t)p * 4096u + (uint32_t)kc_ * 2048u + (uint32_t)r_ * 16u,
                       (const void*)src);
        }
    };
    auto issueB = [&](int q) {
        uint32_t bbuf = sb + (uint32_t)(q & 1) * S8_BBUF;
        for (int e = tid; e < 1280; e += 256) {
            int px = e >> 1, kc = e & 1;
            int pr = px / 40, pc = px - pr * 40;
            const int8_t* src = g_xp_s8 +
                ((size_t)((b * 40 + bh8 + pr) * 40 + pc)) * CC + q * 32 + kc * 16;
            CP_ASYNC16(bbuf + (uint32_t)kc * S8_BSTR + (uint32_t)px * 16u, (const void*)src);
        }
    };

    issueB(0);
    issueRow(0);
    issueRow(1);
    CP_COMMIT();

    for (int R = 0; R < 144; R++) {
        int q = R / 9, dy = R - q * 9;
        if (R + 2 < 144) issueRow(R + 2);
        if (dy == 7 && q < 15) issueB(q + 1);
        CP_COMMIT();
        CP_WAIT1();
        __syncthreads();
        uint32_t rowbase = sb + S8_ABASE + (uint32_t)(R & 3) * S8_ROW;
        uint32_t bbase = sb + (uint32_t)(q & 1) * S8_BBUF;
        for (int dx = 0; dx < 9; dx++) {
            uint32_t abase = rowbase + (uint32_t)dx * 4096u;
            uint32_t a[4][4];
#pragma unroll
            for (int mt = 0; mt < 4; mt++) {
                int arow = mbase + mt * 16 + (lane & 15);
                int kcs = lane >> 4;
                ldsm_x4(a[mt], abase + (uint32_t)kcs * 2048u + (uint32_t)arow * 16u);
            }
#pragma unroll
            for (int ntp = 0; ntp < 4; ntp++) {
                int m = lane >> 3;
                int n_ = nbase + ntp * 16 + ((m & 2) << 2) + (lane & 7);
                int hl = n_ >> 5, w = n_ & 31;
                int kcs = m & 1;
                int px = (hl + dy) * 40 + (w + dx);
                uint32_t bq[4];
                ldsm_x4(bq, bbase + (uint32_t)kcs * S8_BSTR + (uint32_t)px * 16u);
#pragma unroll
                for (int mt = 0; mt < 4; mt++) {
                    mma_s8(acc[mt][2 * ntp],     a[mt], bq);
                    mma_s8(acc[mt][2 * ntp + 1], a[mt], bq + 2);
                }
            }
        }
    }
    // ---- fused squash + max-over-c epilogue ----
    CP_WAIT0();
    __syncthreads();
    float s = (__uint_as_float(g_wmax_bits) * (1.f / 127.f)) *
              (__uint_as_float(g_xmax_bits) * (1.f / 127.f));
    int k_ = lane >> 2;
    float bi[4][2];
#pragma unroll
    for (int mt = 0; mt < 4; mt++) {
        int cl0 = (mbase >> 3) + 2 * mt;
        bi[mt][0] = cb[k_ * 32 + cl0 + 16 * y];
        bi[mt][1] = cb[k_ * 32 + cl0 + 1 + 16 * y];
    }
    float* part = (float*)smem;   // [8 warps][8 k][64 px] = 16KB
#pragma unroll
    for (int nt = 0; nt < 8; nt++) {
#pragma unroll
        for (int jp = 0; jp < 2; jp++) {
            float v[8]; float m_ = -INFINITY;
#pragma unroll
            for (int mt = 0; mt < 4; mt++) {
                v[2 * mt]     = (float)acc[mt][nt][jp]     * s + bi[mt][0];
                v[2 * mt + 1] = (float)acc[mt][nt][jp + 2] * s + bi[mt][1];
            }
#pragma unroll
            for (int e = 0; e < 8; e++) {
                float sq = v[e] * v[e];
                sq += __shfl_xor_sync(0xffffffffu, sq, 4);
                sq += __shfl_xor_sync(0xffffffffu, sq, 8);
                sq += __shfl_xor_sync(0xffffffffu, sq, 16);
                float sf = sq / ((1.f + sq) * sqrtf(sq + 1e-8f));
                m_ = fmaxf(m_, v[e] * sf);
            }
            part[(wid * 8 + k_) * 64 + nt * 8 + (lane & 3) * 2 + jp] = m_;
        }
    }
    __syncthreads();
    if (wid < 4) {
#pragma unroll
        for (int e0 = 0; e0 < 16; e0++) {
            int e = lane * 16 + e0;
            int kk = e >> 6, n = e & 63;
            float m1 = part[(wid * 8 + kk) * 64 + n];
            float m2 = part[((wid + 4) * 8 + kk) * 64 + n];
            g_cap4[((size_t)((y * BB + b) * 8 + kk)) * HWW + pix0 + (wid & 3) * 64 + n]
                = fmaxf(m1, m2);
        }
    }
}

// ================= K5: top-8 candidate pixels per (b,k) =====================
__global__ void k5_top8() {
    int bk = blockIdx.x;
    int b = bk >> 3, k = bk & 7;
    __shared__ float val[1024];
    __shared__ float sv[256];
    __shared__ int   si[256];
    int tid = threadIdx.x;
    for (int hw = tid; hw < HWW; hw += 256)
        val[hw] = fmaxf(g_cap4[bk * HWW + hw],
                        g_cap4[bk * HWW + hw + BB * NCAPS * HWW]);
    __syncthreads();
    for (int j = 0; j < TOPK; j++) {
        float best = -INFINITY; int bi = 0x7fffffff;
        for (int hw = tid; hw < HWW; hw += 256) {
            float v = val[hw];
            if (v > best || (v == best && hw < bi)) { best = v; bi = hw; }
        }
        sv[tid] = best; si[tid] = bi;
        __syncthreads();
        for (int s = 128; s > 0; s >>= 1) {
            if (tid < s) {
                if (sv[tid + s] > sv[tid] ||
                    (sv[tid + s] == sv[tid] && si[tid + s] < si[tid])) {
                    sv[tid] = sv[tid + s]; si[tid] = si[tid + s];
                }
            }
            __syncthreads();
        }
        if (tid == 0) {
            g_slots[b * SLOTS + k * TOPK + j] = si[0];
            val[si[0]] = -INFINITY;
        }
        __syncthreads();
    }
}

// ================= K2b: int16-via-int8 rescore at candidate pixels ==========
#define RB16_STG 12288u
#define K2B_SMEM (4 * 12288 + 256)
__global__ __launch_bounds__(256, 1) void k2b_rescore() {
    extern __shared__ char smem[];
    uint32_t sb = smem_u32(smem);
    int* s_slots = (int*)(smem + 4 * 12288);
    int tid = threadIdx.x, wid = tid >> 5, lane = tid & 31;
    int qs  = blockIdx.x;
    int ocb = blockIdx.y * 128;
    int b   = blockIdx.z;
    int mbase = (wid >> 1) * 32;
    int nbase = (wid & 1) * 32;

    if (tid < SLOTS) s_slots[tid] = g_slots[b * SLOTS + tid];
    __syncthreads();

    int a1[2][4][4], a2[2][4][4];
#pragma unroll
    for (int mt = 0; mt < 2; mt++)
#pragma unroll
        for (int nt = 0; nt < 4; nt++)
#pragma unroll
            for (int j = 0; j < 4; j++) { a1[mt][nt][j] = 0; a2[mt][nt][j] = 0; }

    auto issue = [&](int it) {
        int q = qs * 2 + it / 81;
        int tap = it - (it / 81) * 81;
        int dy = tap / 9, dx = tap - dy * 9;
        uint32_t stg = sb + (uint32_t)(it & 3) * RB16_STG;
#pragma unroll
        for (int p = 0; p < 2; p++) {
            int e = tid + p * 256;
            int plane = e >> 8, r = (e >> 1) & 127, kc = e & 1;
            size_t gsrc = ((size_t)(tap * OC + ocb + r)) * CC + q * 32 + kc * 16;
            const int8_t* src = (plane ? g_w16l : g_w16h) + gsrc;
            CP_ASYNC16(stg + (uint32_t)plane * 4096u + (uint32_t)kc * 2048u + (uint32_t)r * 16u,
                       (const void*)src);
        }
        {
            int e = tid;
            int plane = e >> 7, row = (e >> 1) & 63, kc = e & 1;
            int pix = s_slots[row];
            int yy = pix >> 5, x = pix & 31;
            size_t gsrc = ((size_t)((b * 40 + yy + dy) * 40 + (x + dx))) * CC + q * 32 + kc * 16;
            const int8_t* src = (plane ? g_x16l : g_x16h) + gsrc;
            CP_ASYNC16(stg + 8192u + (uint32_t)plane * 2048u + (uint32_t)kc * 1024u + (uint32_t)row * 16u,
                       (const void*)src);
        }
    };

    issue(0);
    issue(1);
    CP_COMMIT();
    const int NIT = 2 * TAPS;
    for (int it = 0; it < NIT; it++) {
        if (it + 2 < NIT) issue(it + 2);
        CP_COMMIT();
        CP_WAIT1();
        __syncthreads();
        uint32_t stg = sb + (uint32_t)(it & 3) * RB16_STG;
        uint32_t ah[2][4], al[2][4];
#pragma unroll
        for (int mt = 0; mt < 2; mt++) {
            int arow = mbase + mt * 16 + (lane & 15);
            int kcs = lane >> 4;
            uint32_t so = (uint32_t)kcs * 2048u + (uint32_t)arow * 16u;
            ldsm_x4(ah[mt], stg + so);
            ldsm_x4(al[mt], stg + 4096u + so);
        }
#pragma unroll
        for (int ntp = 0; ntp < 2; ntp++) {
            int m = lane >> 3;
            int row = nbase + ntp * 16 + ((m & 2) << 2) + (lane & 7);
            int kcs = m & 1;
            uint32_t so = (uint32_t)kcs * 1024u + (uint32_t)row * 16u;
            uint32_t bh[4], bl[4];
            ldsm_x4(bh, stg + 8192u + so);
            ldsm_x4(bl, stg + 8192u + 2048u + so);
#pragma unroll
            for (int mt = 0; mt < 2; mt++) {
                mma_s8(a1[mt][2 * ntp],     ah[mt], bh);
                mma_s8(a2[mt][2 * ntp],     ah[mt], bl);
                mma_s8(a2[mt][2 * ntp],     al[mt], bh);
                mma_s8(a1[mt][2 * ntp + 1], ah[mt], bh + 2);
                mma_s8(a2[mt][2 * ntp + 1], ah[mt], bl + 2);
                mma_s8(a2[mt][2 * ntp + 1], al[mt], bh + 2);
            }
        }
    }
    float swx = (__uint_as_float(g_wmax_bits) * (1.f / 32639.f)) *
                (__uint_as_float(g_xmax_bits) * (1.f / 32639.f));
#pragma unroll
    for (int mt = 0; mt < 2; mt++) {
        int m0 = ocb + mbase + mt * 16 + (lane >> 2);
        float* d0 = g_rpart + ((size_t)((qs * BB + b) * OC + m0)) * SLOTS;
        float* d1 = d0 + 8 * SLOTS;
#pragma unroll
        for (int nt = 0; nt < 4; nt++) {
            int n = nbase + nt * 8 + (lane & 3) * 2;
            d0[n]     = fmaf(65536.f, (float)a1[mt][nt][0], 256.f * (float)a2[mt][nt][0]) * swx;
            d0[n + 1] = fmaf(65536.f, (float)a1[mt][nt][1], 256.f * (float)a2[mt][nt][1]) * swx;
            d1[n]     = fmaf(65536.f, (float)a1[mt][nt][2], 256.f * (float)a2[mt][nt][2]) * swx;
            d1[n + 1] = fmaf(65536.f, (float)a1[mt][nt][3], 256.f * (float)a2[mt][nt][3]) * swx;
        }
    }
}

// ================= K2c ======================================================
#define K2C_SMEM (OC * SLOTS * 4 + NCAPS * SLOTS * 4 + SLOTS * 4)
__global__ __launch_bounds__(256) void k2c_pick(const float* __restrict__ cb) {
    extern __shared__ char smem[];
    float* v     = (float*)smem;
    float* sval  = (float*)(smem + OC * SLOTS * 4);
    int*   sl    = (int*)(smem + OC * SLOTS * 4 + NCAPS * SLOTS * 4);
    int b = blockIdx.x, tid = threadIdx.x;
    if (tid < SLOTS) sl[tid] = g_slots[b * SLOTS + tid];
    for (int idx = tid; idx < OC * SLOTS; idx += 256) {
        int oc = idx >> 6;
        float s = cb[oc];
#pragma unroll
        for (int qs = 0; qs < KSPLIT; qs++)
            s += g_rpart[((size_t)((qs * BB + b) * OC)) * SLOTS + idx];
        v[idx] = s;
    }
    __syncthreads();
    if (tid < SLOTS) {
        float mk[8];
#pragma unroll
        for (int k = 0; k < 8; k++) mk[k] = -INFINITY;
        for (int c = 0; c < CAPC; c++) {
            float vv[8]; float sq = 0.f;
#pragma unroll
            for (int k = 0; k < 8; k++) {
                vv[k] = v[(k * CAPC + c) * SLOTS + tid];
                sq += vv[k] * vv[k];
            }
            float sf = sq / ((1.f + sq) * sqrtf(sq + 1e-8f));
#pragma unroll
            for (int k = 0; k < 8; k++) mk[k] = fmaxf(mk[k], vv[k] * sf);
        }
#pragma unroll
        for (int k = 0; k < 8; k++) sval[k * SLOTS + tid] = mk[k];
    }
    __syncthreads();
    if (tid < NCAPS) {
        float best = -INFINITY; int bp = 0x7fffffff;
        for (int s = 0; s < SLOTS; s++) {
            float vv = sval[tid * SLOTS + s];
            int px = sl[s];
            if (vv > best || (vv == best && px < bp)) { best = vv; bp = px; }
        }
        g_idx[b * NCAPS + tid] = bp;
    }
}

// ================= K6..K12 (exact path) =====================================
__global__ void k6_smean() {
    int i = blockIdx.x * 256 + threadIdx.x;
    int c = i >> 3, k = i & 7;
    float s = 0.f;
    for (int b = 0; b < BB; b++) {
        int hw = g_idx[b * 8 + k];
        float n = fmaxf(g_norm[b * HWW + hw], 1e-12f);
        s += g_x[((size_t)(b * CC + c)) * HWW + hw] / n;
    }
    g_smean[c * 8 + k] = s * (1.f / 16.f);
}

__global__ __launch_bounds__(128) void k7_cm() {
    __shared__ float ss[CC * 8];
    for (int e = threadIdx.x; e < CC * 8; e += 128) ss[e] = g_smean[e];
    __syncthreads();
    int i = blockIdx.x * 128 + threadIdx.x;
    int b = i >> 10, hw = i & 1023;
    const float* xp = g_x + (size_t)b * CC * HWW + hw;
    float acc[8] = {};
    for (int c = 0; c < CC; c++) {
        float xv = xp[c * HWW];
#pragma unroll
        for (int k = 0; k < 8; k++) acc[k] += xv * ss[c * 8 + k];
    }
    float inv = 1.f / fmaxf(g_norm[i], 1e-12f);
#pragma unroll
    for (int k = 0; k < 8; k++) g_cm[(b * 8 + k) * HWW + hw] = acc[k] * inv;
}

__global__ void k8_minmax() {
    int bk = blockIdx.x;
    __shared__ float smn[256], smx[256];
    int tid = threadIdx.x;
    float mn = INFINITY, mx = -INFINITY;
    for (int hw = tid; hw < HWW; hw += 256) {
        float v = g_cm[bk * HWW + hw];
        mn = fminf(mn, v); mx = fmaxf(mx, v);
    }
    smn[tid] = mn; smx[tid] = mx;
    __syncthreads();
    for (int s = 128; s > 0; s >>= 1) {
        if (tid < s) {
            smn[tid] = fminf(smn[tid], smn[tid + s]);
            smx[tid] = fmaxf(smx[tid], smx[tid + s]);
        }
        __syncthreads();
    }
    if (tid == 0) { g_mm[bk * 2] = smn[0]; g_mm[bk * 2 + 1] = smx[0]; }
}

__global__ void k9_cmnorm() {
    int i = blockIdx.x * 128 + threadIdx.x;
    int b = i >> 10, hw = i & 1023;
    float s = 0.f;
#pragma unroll
    for (int k = 0; k < 8; k++) {
        int bk = b * 8 + k;
        float mn = g_mm[bk * 2], mx = g_mm[bk * 2 + 1];
        float v = (g_cm[bk * HWW + hw] - mn) / (mx - mn + 1e-12f);
        g_cm[bk * HWW + hw] = v;
        s += v;
    }
    g_cmmean[i] = s * 0.125f;
}

__global__ __launch_bounds__(256) void k10_proto() {
    int c0 = blockIdx.x * 8;
    int tid = threadIdx.x, wid = tid >> 5, lane = tid & 31;
    float acc[8][8];
#pragma unroll
    for (int cl = 0; cl < 8; cl++)
#pragma unroll
        for (int k = 0; k < 8; k++) acc[cl][k] = 0.f;
    for (int i = tid; i < BB * HWW; i += 256) {
        int b = i >> 10, hw = i & 1023;
        float cmv[8];
#pragma unroll
        for (int k = 0; k < 8; k++) cmv[k] = g_cm[(b * 8 + k) * HWW + hw];
#pragma unroll
        for (int cl = 0; cl < 8; cl++) {
            float xv = g_x[((size_t)(b * CC + c0 + cl)) * HWW + hw];
#pragma unroll
            for (int k = 0; k < 8; k++) acc[cl][k] += xv * cmv[k];
        }
    }
    __shared__ float wred[8][64];
#pragma unroll
    for (int cl = 0; cl < 8; cl++)
#pragma unroll
        for (int k = 0; k < 8; k++) {
            float v = acc[cl][k];
#pragma unroll
            for (int off = 16; off; off >>= 1)
                v += __shfl_xor_sync(0xffffffffu, v, off);
            if (lane == 0) wred[wid][cl * 8 + k] = v;
        }
    __syncthreads();
    if (tid < 64) {
        float s = 0.f;
#pragma unroll
        for (int w = 0; w < 8; w++) s += wred[w][tid];
        int cl = tid >> 3, k = tid & 7;
        g_proto[k * CC + c0 + cl] = s * (1.f / (BB * HWW));
    }
}

__global__ void k11_pm(float* __restrict__ out) {
    int c = threadIdx.x;
    float s = 0.f;
#pragma unroll
    for (int k = 0; k < 8; k++) s += g_proto[k * CC + c];
    s *= 0.125f;
    g_pm[c] = s;
    __shared__ float red[512];
    red[c] = s * s;
    __syncthreads();
    for (int st = 256; st > 0; st >>= 1) {
        if (c < st) red[c] += red[c + st];
        __syncthreads();
    }
    float nrm = fmaxf(sqrtf(red[0]), 1e-12f);
    out[c] = s / nrm;
}

__global__ __launch_bounds__(128) void k12_out(float* __restrict__ out) {
    __shared__ float spm[CC];
    for (int e = threadIdx.x; e < CC; e += 128) spm[e] = g_pm[e];
    __syncthreads();
    int i = blockIdx.x * 128 + threadIdx.x;
    int b = i >> 10, hw = i & 1023;
    float cmm = g_cmmean[i];
    const float* xp = g_x + (size_t)b * CC * HWW + hw;
    float ss2 = 0.f;
    for (int c = 0; c < CC; c++) {
        float v = xp[c * HWW] * (spm[c] + cmm);
        ss2 += v * v;
    }
    float inv = 1.f / fmaxf(sqrtf(ss2), 1e-12f);
    float* op = out + CC + (size_t)b * CC * HWW + hw;
    for (int c = 0; c < CC; c++)
        op[c * HWW] = xp[c * HWW] * (spm[c] + cmm) * inv;
}

// ================= launcher ==================================================
extern "C" void kernel_launch(void* const* d_in, const int* in_sizes, int n_in,
                              void* d_out, int out_size) {
    const float* x5     = (const float*)d_in[0];
    const float* conv_w = (const float*)d_in[1];
    const float* conv_b = (const float*)d_in[2];
    const float* caps_w = (const float*)d_in[3];
    const float* caps_b = (const float*)d_in[4];
    float* out = (float*)d_out;
    (void)in_sizes; (void)n_in; (void)out_size;

    cudaFuncSetAttribute(k1_mma,      cudaFuncAttributeMaxDynamicSharedMemorySize, K1_SMEM);
    cudaFuncSetAttribute(k2a_s8,      cudaFuncAttributeMaxDynamicSharedMemorySize, K2A_SMEM);
    cudaFuncSetAttribute(k2b_rescore, cudaFuncAttributeMaxDynamicSharedMemorySize, K2B_SMEM);
    cudaFuncSetAttribute(k2c_pick,    cudaFuncAttributeMaxDynamicSharedMemorySize, K2C_SMEM);

    kp_pre  <<<1536, 256>>>(x5, conv_w);
    kp_w    <<<2048, 256>>>(caps_w);
    kp_wq   <<<5184, 256>>>();
    k1_mma  <<<dim3(4, 4, 16), 256, K1_SMEM>>>(x5, conv_b);
    kp_x    <<<dim3(32, 16), 256>>>();
    k2a_s8  <<<dim3(4, 2, 16), 256, K2A_SMEM>>>(caps_b);
    k5_top8 <<<128, 256>>>();
    k2b_rescore<<<dim3(KSPLIT, 2, 16), 256, K2B_SMEM>>>();
    k2c_pick<<<16, 256, K2C_SMEM>>>(caps_b);
    k6_smean<<<16, 256>>>();
    k7_cm   <<<128, 128>>>();
    k8_minmax<<<128, 256>>>();
    k9_cmnorm<<<128, 128>>>();
    k10_proto<<<64, 256>>>();
    k11_pm  <<<1, 512>>>(out);
    k12_out <<<128, 128>>>(out);
}